// round 9
// baseline (speedup 1.0000x reference)
#include <cuda_runtime.h>
#include <cuda_bf16.h>
#include <cuda_fp16.h>
#include <cstdint>

#define B_   8
#define C_   64
#define N_   4096
#define K_   20
#define M_   8
#define OUTC 64
#define CM   512
#define NEG_SLOPE 0.2f

__device__ float           g_ft[B_ * N_ * C_];
__device__ float           g_xt[B_ * N_ * 4];
__device__ __nv_bfloat16   g_w_hi[OUTC * CM];
__device__ __nv_bfloat16   g_w_lo[OUTC * CM];
__device__ int             g_idx_is64;

#define FMA2(d, a, b) \
    asm volatile("fma.rn.f32x2 %0, %1, %2, %0;" : "+l"(d) : "l"(a), "l"(b))
#define PACK_BCAST(dst, v) do { unsigned r_ = __float_as_uint(v); \
    asm("mov.b64 %0, {%1,%2};" : "=l"(dst) : "r"(r_), "r"(r_)); } while (0)
#define PACKF2(dst, lo, hi) do { unsigned lo_ = __float_as_uint(lo), hi_ = __float_as_uint(hi); \
    asm("mov.b64 %0, {%1,%2};" : "=l"(dst) : "r"(lo_), "r"(hi_)); } while (0)
#define UNPACK2(lo, hi, v) do { unsigned lo_, hi_; \
    asm("mov.b64 {%0,%1}, %2;" : "=r"(lo_), "=r"(hi_) : "l"(v)); \
    lo = __uint_as_float(lo_); hi = __uint_as_float(hi_); } while (0)

// ----------------------------------------------------------------------------
// Kernel P: fused prep (identical to R8)
// ----------------------------------------------------------------------------
__global__ void __launch_bounds__(256)
prep_kernel(const float* __restrict__ feature, const float* __restrict__ W,
            const float* __restrict__ x, const int* __restrict__ rawidx) {
    __shared__ float tile[32][133];
    int bid = blockIdx.x;
    int t = threadIdx.x;

    if (bid < 512) {
        int b  = bid >> 6;
        int rem = bid & 63;
        int c0 = (rem >> 5) * 32;
        int n0 = (rem & 31) * 128;
        int cy = t >> 5, nx = (t & 31) * 4;
#pragma unroll
        for (int p = 0; p < 4; p++) {
            int c = c0 + cy + p * 8;
            float4 v = *(const float4*)&feature[((size_t)b * C_ + c) * N_ + n0 + nx];
            tile[cy + p * 8][nx]     = v.x;
            tile[cy + p * 8][nx + 1] = v.y;
            tile[cy + p * 8][nx + 2] = v.z;
            tile[cy + p * 8][nx + 3] = v.w;
        }
        __syncthreads();
        int c4 = (t & 7) * 4;
#pragma unroll
        for (int it = 0; it < 4; it++) {
            int n = (t >> 3) + it * 32;
            float4 v = make_float4(tile[c4][n], tile[c4 + 1][n],
                                   tile[c4 + 2][n], tile[c4 + 3][n]);
            *(float4*)&g_ft[((size_t)b * N_ + n0 + n) * C_ + c0 + c4] = v;
        }
    } else if (bid < 640) {
        int i = (bid - 512) * 256 + t;
        float w = W[i];
        __nv_bfloat16 h = __float2bfloat16(w);
        g_w_hi[i] = h;
        g_w_lo[i] = __float2bfloat16(w - __bfloat162float(h));
    } else if (bid < 768) {
        int r = bid - 640;
        int b = r >> 4;
        int n = (r & 15) * 256 + t;
        const float* xb = x + (size_t)b * 3 * N_;
        *(float4*)&g_xt[((size_t)b * N_ + n) * 4] =
            make_float4(xb[n], xb[N_ + n], xb[2 * N_ + n], 0.0f);
    } else {
        if (t == 0) {
            int all0 = 1;
#pragma unroll
            for (int j = 1; j < 64; j += 2)
                if (rawidx[j] != 0) all0 = 0;
            g_idx_is64 = all0;
        }
    }
}

// ----------------------------------------------------------------------------
// Fused kernel: perm+softmax+agg (produce) + tensor GEMM (consume) + epilogue
// 128 points/CTA, 8 chunks of 8 channels (64 k each = 2 sub-stages of 32 k)
// ----------------------------------------------------------------------------
#define ASTR     40
#define SOS      132
#define OFF_PH   10240                   // sIdx [128][20] int at 0
#define OFF_A    51200                   // sPh [128][20][8] half at 10240
#define OFF_W    92160                   // A: hi[2][128][40], lo +20480
#define SMEMSZ   112640                  // W: hi[2][64][40],  lo +10240

#define LDSM4(R0, R1, R2, R3, addr)                                        \
    asm volatile("ldmatrix.sync.aligned.m8n8.x4.shared.b16 {%0,%1,%2,%3}, [%4];" \
                 : "=r"(R0), "=r"(R1), "=r"(R2), "=r"(R3) : "r"(addr))
#define MMA(d, a, b0v, b1v)                                                \
    asm volatile("mma.sync.aligned.m16n8k16.row.col.f32.bf16.bf16.f32 "    \
                 "{%0,%1,%2,%3}, {%4,%5,%6,%7}, {%8,%9}, {%0,%1,%2,%3};"   \
                 : "+f"(d[0]), "+f"(d[1]), "+f"(d[2]), "+f"(d[3])          \
                 : "r"(a[0]), "r"(a[1]), "r"(a[2]), "r"(a[3]),             \
                   "r"(b0v), "r"(b1v))
#define CPA(saddr, gptr)                                                   \
    asm volatile("cp.async.cg.shared.global [%0], [%1], 16;"               \
                 :: "r"(saddr), "l"(gptr))

#define ISSUE_W(ch) do {                                                   \
    if (t < 128) {                                                         \
        int oc_ = t >> 1, seg_ = (t & 1) * 16;                             \
        uint32_t so_ = (uint32_t)(oc_ * ASTR + seg_) * 2;                  \
        _Pragma("unroll")                                                  \
        for (int sub_ = 0; sub_ < 2; sub_++) {                             \
            const __nv_bfloat16* gh_ = g_w_hi + oc_ * CM + (ch) * 64 + sub_ * 32 + seg_; \
            const __nv_bfloat16* gl_ = g_w_lo + oc_ * CM + (ch) * 64 + sub_ * 32 + seg_; \
            uint32_t wb_ = sb + OFF_W + sub_ * 5120 + so_;                 \
            CPA(wb_, gh_);            CPA(wb_ + 16, gh_ + 8);              \
            CPA(wb_ + 10240, gl_);    CPA(wb_ + 10240 + 16, gl_ + 8);      \
        }                                                                  \
    }                                                                      \
    asm volatile("cp.async.commit_group;");                                \
} while (0)

extern __shared__ unsigned char g_dsm[];

__global__ void __launch_bounds__(256)
fused_kernel(const void* __restrict__ nidx, const float* __restrict__ kern,
             const float* __restrict__ bias, const float* __restrict__ feature,
             float* __restrict__ out) {
    int t  = threadIdx.x;
    int q0 = blockIdx.x * 128;
    int b  = q0 >> 12;
    int n0 = q0 & (N_ - 1);
    uint32_t sb = (uint32_t)__cvta_generic_to_shared(g_dsm);

    int*    sIdx = (int*)g_dsm;               // [128][20]
    __half* sPh  = (__half*)(g_dsm + OFF_PH); // [128][20][8]

    ISSUE_W(0);

    // phase 0: indices
    int is64 = g_idx_is64;
    for (int it = t; it < 128 * K_; it += 256) {
        int p = it / K_, k = it - p * K_;
        size_t pos = (size_t)(q0 + p) * K_ + k;
        int i = is64 ? (int)((const long long*)nidx)[pos] : ((const int*)nidx)[pos];
        sIdx[p * K_ + k] = i & (N_ - 1);
    }
    __syncthreads();

    // phase 1: perm + softmax per (point, m-pair), logits in registers
    for (int it = t; it < 512; it += 256) {
        int p = it >> 2, m0 = (it & 3) * 2;
        float ka0 = kern[m0],     ka1 = kern[M_ + m0],     ka2 = kern[2 * M_ + m0];
        float kb0 = kern[m0 + 1], kb1 = kern[M_ + m0 + 1], kb2 = kern[2 * M_ + m0 + 1];
        int i0 = sIdx[p * K_];
        float4 x0v = *(const float4*)&g_xt[((size_t)b * N_ + i0) * 4];
        float va[K_], vb[K_];
#pragma unroll
        for (int k = 0; k < K_; k++) {
            float4 xv = *(const float4*)&g_xt[((size_t)b * N_ + sIdx[p * K_ + k]) * 4];
            float x0 = xv.x - x0v.x, x1 = xv.y - x0v.y, x2 = xv.z - x0v.z;
            va[k] = x0 * ka0 + x1 * ka1 + x2 * ka2;
            vb[k] = x0 * kb0 + x1 * kb1 + x2 * kb2;
        }
        if (m0 == 0) va[0] += 1.0f;
        float mxa = -1e30f, mxb = -1e30f;
#pragma unroll
        for (int k = 0; k < K_; k++) { mxa = fmaxf(mxa, va[k]); mxb = fmaxf(mxb, vb[k]); }
        float sa = 0.0f, sc = 0.0f;
#pragma unroll
        for (int k = 0; k < K_; k++) {
            va[k] = __expf(va[k] - mxa); sa += va[k];
            vb[k] = __expf(vb[k] - mxb); sc += vb[k];
        }
        float ia = 1.0f / sa, ib = 1.0f / sc;
#pragma unroll
        for (int k = 0; k < K_; k++) {
            __half2 hv = __floats2half2_rn(va[k] * ia, vb[k] * ib);
            *(__half2*)&sPh[(p * K_ + k) * M_ + m0] = hv;
        }
    }

    // D accumulators (persist across chunks)
    float acc[2][4][4];
#pragma unroll
    for (int mi = 0; mi < 2; mi++)
#pragma unroll
        for (int nt = 0; nt < 4; nt++)
#pragma unroll
            for (int j = 0; j < 4; j++) acc[mi][nt][j] = 0.0f;

    int w = t >> 5, l = t & 31;
    int mw = w & 3, nw = w >> 2;
    int ptb = mw * 32, ocb = nw * 32;
    int aRow = ptb + (l & 15);
    int aCol = (l >> 4) * 8;
    int bRow = ocb + ((l >> 4) * 8) + (l & 7);
    int bCol = ((l >> 3) & 1) * 8;

    int pp = t >> 1, h = t & 1;          // produce: point pp, channels h*4..h*4+3

    for (int ch = 0; ch < 8; ch++) {
        __syncthreads();                 // sPh ready (ch=0) / prev consume done

        // ---- produce: A tile for channels [ch*8, ch*8+8) ----
        uint64_t a2[4][4];
#pragma unroll
        for (int c = 0; c < 4; c++)
#pragma unroll
            for (int j = 0; j < 4; j++) a2[c][j] = 0;

        const float* ftb = g_ft + (size_t)b * N_ * C_ + ch * 8 + h * 4;
#pragma unroll
        for (int kb = 0; kb < K_; kb += 4) {
            float4 f4[4]; uint4 p4[4];
#pragma unroll
            for (int j = 0; j < 4; j++)
                f4[j] = *(const float4*)(ftb + (size_t)sIdx[pp * K_ + kb + j] * C_);
#pragma unroll
            for (int j = 0; j < 4; j++)
                p4[j] = *(const uint4*)&sPh[(pp * K_ + kb + j) * M_];
#pragma unroll
            for (int j = 0; j < 4; j++) {
                float2 q0v = __half22float2(*(const __half2*)&p4[j].x);
                float2 q1v = __half22float2(*(const __half2*)&p4[j].y);
                float2 q2v = __half22float2(*(const __half2*)&p4[j].z);
                float2 q3v = __half22float2(*(const __half2*)&p4[j].w);
                uint64_t d0, d1, d2, d3;
                PACKF2(d0, q0v.x, q0v.y); PACKF2(d1, q1v.x, q1v.y);
                PACKF2(d2, q2v.x, q2v.y); PACKF2(d3, q3v.x, q3v.y);
                float fc[4] = {f4[j].x, f4[j].y, f4[j].z, f4[j].w};
#pragma unroll
                for (int c = 0; c < 4; c++) {
                    uint64_t fb;
                    PACK_BCAST(fb, fc[c]);
                    FMA2(a2[c][0], fb, d0); FMA2(a2[c][1], fb, d1);
                    FMA2(a2[c][2], fb, d2); FMA2(a2[c][3], fb, d3);
                }
            }
        }
        // split hi/lo, store rows: sub-tile h, row pp, elems c*8..c*8+7
        uint32_t abase = sb + OFF_A + h * 10240 + (uint32_t)(pp * ASTR) * 2;
#pragma unroll
        for (int c = 0; c < 4; c++) {
            float v[8];
#pragma unroll
            for (int j = 0; j < 4; j++) UNPACK2(v[2 * j], v[2 * j + 1], a2[c][j]);
            uint32_t hp[4], lp[4];
#pragma unroll
            for (int j = 0; j < 4; j++) {
                __nv_bfloat16 h0 = __float2bfloat16(v[2 * j]);
                __nv_bfloat16 h1 = __float2bfloat16(v[2 * j + 1]);
                __nv_bfloat16 l0 = __float2bfloat16(v[2 * j]     - __bfloat162float(h0));
                __nv_bfloat16 l1 = __float2bfloat16(v[2 * j + 1] - __bfloat162float(h1));
                hp[j] = ((uint32_t)__bfloat16_as_ushort(h1) << 16) | __bfloat16_as_ushort(h0);
                lp[j] = ((uint32_t)__bfloat16_as_ushort(l1) << 16) | __bfloat16_as_ushort(l0);
            }
            asm volatile("st.shared.v4.b32 [%0], {%1,%2,%3,%4};" ::
                "r"(abase + c * 16), "r"(hp[0]), "r"(hp[1]), "r"(hp[2]), "r"(hp[3]));
            asm volatile("st.shared.v4.b32 [%0], {%1,%2,%3,%4};" ::
                "r"(abase + 20480 + c * 16), "r"(lp[0]), "r"(lp[1]), "r"(lp[2]), "r"(lp[3]));
        }
        asm volatile("cp.async.wait_group 0;");
        __syncthreads();

        // ---- consume: 2 sub-stages of 32 k ----
#pragma unroll
        for (int sub = 0; sub < 2; sub++) {
            uint32_t baH = sb + OFF_A + sub * 10240;
            uint32_t baL = baH + 20480;
            uint32_t bwH = sb + OFF_W + sub * 5120;
            uint32_t bwL = bwH + 10240;
#pragma unroll
            for (int step = 0; step < 2; step++) {
                int koff = step * 16;
                uint32_t Ah[2][4], Al[2][4], Bh[2][4], Bl[2][4];
#pragma unroll
                for (int mi = 0; mi < 2; mi++) {
                    uint32_t off = (uint32_t)((aRow + mi * 16) * ASTR + aCol + koff) * 2;
                    LDSM4(Ah[mi][0], Ah[mi][1], Ah[mi][2], Ah[mi][3], baH + off);
                    LDSM4(Al[mi][0], Al[mi][1], Al[mi][2], Al[mi][3], baL + off);
                }
#pragma unroll
                for (int ni2 = 0; ni2 < 2; ni2++) {
                    uint32_t off = (uint32_t)((bRow + ni2 * 16) * ASTR + bCol + koff) * 2;
                    LDSM4(Bh[ni2][0], Bh[ni2][1], Bh[ni2][2], Bh[ni2][3], bwH + off);
                    LDSM4(Bl[ni2][0], Bl[ni2][1], Bl[ni2][2], Bl[ni2][3], bwL + off);
                }
#pragma unroll
                for (int mi = 0; mi < 2; mi++) {
#pragma unroll
                    for (int nt = 0; nt < 4; nt++) {
                        int ni2 = nt >> 1, sel = (nt & 1) * 2;
                        MMA(acc[mi][nt], Ah[mi], Bh[ni2][sel], Bh[ni2][sel + 1]);
                        MMA(acc[mi][nt], Ah[mi], Bl[ni2][sel], Bl[ni2][sel + 1]);
                        MMA(acc[mi][nt], Al[mi], Bh[ni2][sel], Bh[ni2][sel + 1]);
                    }
                }
            }
        }
        __syncthreads();
        if (ch + 1 < 8) ISSUE_W(ch + 1);
    }

    // ---- epilogue (reuses sIdx/sPh region) ----
    float* sOut = (float*)g_dsm;
    int g2 = l >> 2, t4 = l & 3;
#pragma unroll
    for (int mi = 0; mi < 2; mi++) {
#pragma unroll
        for (int nt = 0; nt < 4; nt++) {
            int pt = ptb + mi * 16 + g2;
            int oc = ocb + nt * 8 + 2 * t4;
            sOut[oc * SOS + pt]           = acc[mi][nt][0];
            sOut[(oc + 1) * SOS + pt]     = acc[mi][nt][1];
            sOut[oc * SOS + pt + 8]       = acc[mi][nt][2];
            sOut[(oc + 1) * SOS + pt + 8] = acc[mi][nt][3];
        }
    }
    __syncthreads();

#pragma unroll
    for (int r = 0; r < 8; r++) {
        int oc = w * 8 + r;
        float bs = bias[oc];
        float4 v = *(float4*)&sOut[oc * SOS + l * 4];
        size_t go = ((size_t)(b * OUTC + oc)) * N_ + n0 + l * 4;
        float4 f = *(const float4*)&feature[go];
        v.x += bs; v.x = (v.x > 0.f) ? v.x : NEG_SLOPE * v.x; v.x += f.x;
        v.y += bs; v.y = (v.y > 0.f) ? v.y : NEG_SLOPE * v.y; v.y += f.y;
        v.z += bs; v.z = (v.z > 0.f) ? v.z : NEG_SLOPE * v.z; v.z += f.z;
        v.w += bs; v.w = (v.w > 0.f) ? v.w : NEG_SLOPE * v.w; v.w += f.w;
        *(float4*)&out[go] = v;
    }
}

// ----------------------------------------------------------------------------
extern "C" void kernel_launch(void* const* d_in, const int* in_sizes, int n_in,
                              void* d_out, int out_size) {
    const float* x       = (const float*)d_in[0];
    const float* feature = (const float*)d_in[1];
    const void*  nidx    = d_in[2];
    const float* kern    = (const float*)d_in[3];
    const float* W       = (const float*)d_in[4];
    const float* bias    = (const float*)d_in[5];
    float*       out     = (float*)d_out;

    cudaFuncSetAttribute(fused_kernel,
                         cudaFuncAttributeMaxDynamicSharedMemorySize, SMEMSZ);

    prep_kernel<<<769, 256>>>(feature, W, x, (const int*)nidx);
    fused_kernel<<<(B_ * N_) / 128, 256, SMEMSZ>>>(nidx, kern, bias, feature, out);
}